// round 1
// baseline (speedup 1.0000x reference)
#include <cuda_runtime.h>
#include <math.h>

// Problem constants (fixed by the dataset)
#define B_TOTAL 8192
#define T_STEPS 60
#define F_IN    158
#define HDIM    32
#define G4      128          // 4*H gate columns
#define M_TILE  64           // batch rows per CTA
#define NTHREADS 256
#define XPAD    66           // [k][m] row stride for x / h tiles (2-way max write conflict, 8B-aligned pair reads)

// Shared memory layout (in floats)
#define OFF_WIH0 0                       // [158][128] transposed W_ih0
#define OFF_WHH0 (OFF_WIH0 + F_IN*G4)    // 20224 + [32][128]
#define OFF_WIH1 (OFF_WHH0 + HDIM*G4)    // + [32][128]
#define OFF_WHH1 (OFF_WIH1 + HDIM*G4)    // + [32][128]
#define OFF_XT   (OFF_WHH1 + HDIM*G4)    // [158][66] x tile, transposed
#define OFF_H1   (OFF_XT + F_IN*XPAD)    // [32][66]
#define OFF_H2   (OFF_H1 + HDIM*XPAD)    // [32][66]
#define SMEM_FLOATS (OFF_H2 + HDIM*XPAD)
#define SMEM_BYTES  (SMEM_FLOATS * 4)

typedef unsigned long long u64;

__device__ __forceinline__ void ffma2(u64 &acc, u64 a, u64 b) {
    asm("fma.rn.f32x2 %0, %1, %2, %0;" : "+l"(acc) : "l"(a), "l"(b));
}
__device__ __forceinline__ u64 pack2(float x) {
    u64 r; asm("mov.b64 %0, {%1, %1};" : "=l"(r) : "f"(x)); return r;
}
__device__ __forceinline__ float2 unpack2(u64 v) {
    float2 r; asm("mov.b64 {%0, %1}, %2;" : "=f"(r.x), "=f"(r.y) : "l"(v)); return r;
}

__device__ __forceinline__ float sigf(float x) {
    float e = __expf(-x);                       // x<<0 -> e=inf -> result 0 (ok)
    return __fdividef(1.0f, 1.0f + e);
}
__device__ __forceinline__ float tanhf_(float x) {
    float ax = fabsf(x);
    float e = __expf(-2.0f * ax);               // e in (0,1], no overflow path
    float t = __fdividef(1.0f - e, 1.0f + e);
    return copysignf(t, x);
}

// Accumulate gates[j + 32g][m0..m0+7] += sum_k in[k][m] * W[k][col]
// in: [k][m] layout, row stride XPAD; W: [k][128] layout. Lane owns column j (+32g).
template<int K>
__device__ __forceinline__ void gemm_part(const float* __restrict__ xp,
                                          const float* __restrict__ wp,
                                          u64 acc[4][4]) {
#pragma unroll 4
    for (int k = 0; k < K; ++k) {
        u64 a0 = *(const u64*)(xp + 0);
        u64 a1 = *(const u64*)(xp + 2);
        u64 a2 = *(const u64*)(xp + 4);
        u64 a3 = *(const u64*)(xp + 6);
#pragma unroll
        for (int g = 0; g < 4; ++g) {
            u64 wv = pack2(wp[g * 32]);
            ffma2(acc[g][0], a0, wv);
            ffma2(acc[g][1], a1, wv);
            ffma2(acc[g][2], a2, wv);
            ffma2(acc[g][3], a3, wv);
        }
        xp += XPAD;
        wp += G4;
    }
}

// Pointwise LSTM cell for 8 batch rows of hidden unit j; writes new h to smem row.
__device__ __forceinline__ void cell_update(u64 acc[4][4], float c[8], float* __restrict__ hrow) {
#pragma unroll
    for (int mp = 0; mp < 4; ++mp) {
        float2 iv = unpack2(acc[0][mp]);
        float2 fv = unpack2(acc[1][mp]);
        float2 gv = unpack2(acc[2][mp]);
        float2 ov = unpack2(acc[3][mp]);
        float c0 = sigf(fv.x) * c[2 * mp]     + sigf(iv.x) * tanhf_(gv.x);
        float c1 = sigf(fv.y) * c[2 * mp + 1] + sigf(iv.y) * tanhf_(gv.y);
        c[2 * mp]     = c0;
        c[2 * mp + 1] = c1;
        float2 hv;
        hv.x = sigf(ov.x) * tanhf_(c0);
        hv.y = sigf(ov.y) * tanhf_(c1);
        *(float2*)(hrow + 2 * mp) = hv;
    }
}

__global__ void __launch_bounds__(NTHREADS)
lstm2_fused_kernel(const float* __restrict__ x,
                   const float* __restrict__ Wih0,
                   const float* __restrict__ Whh0,
                   const float* __restrict__ Wih1,
                   const float* __restrict__ Whh1,
                   const float* __restrict__ W1,
                   const float* __restrict__ b1,
                   const float* __restrict__ W2,
                   float* __restrict__ out) {
    extern __shared__ float sm[];
    float* sWih0 = sm + OFF_WIH0;
    float* sWhh0 = sm + OFF_WHH0;
    float* sWih1 = sm + OFF_WIH1;
    float* sWhh1 = sm + OFF_WHH1;
    float* xsT   = sm + OFF_XT;
    float* h1s   = sm + OFF_H1;
    float* h2s   = sm + OFF_H2;

    const int tid = threadIdx.x;
    const int j   = tid & 31;        // hidden unit / gate column owned by this lane
    const int wrp = tid >> 5;        // warp id -> batch sub-tile
    const int m0  = wrp * 8;
    const int b0  = blockIdx.x * M_TILE;

    // Load & transpose weights into SMEM: s[k][n] = W[n][k]
    for (int i = tid; i < G4 * F_IN; i += NTHREADS) {
        int n = i / F_IN, k = i - n * F_IN;
        sWih0[k * G4 + n] = Wih0[i];
    }
    for (int i = tid; i < G4 * HDIM; i += NTHREADS) {
        int n = i >> 5, k = i & 31;
        sWhh0[k * G4 + n] = Whh0[i];
        sWih1[k * G4 + n] = Wih1[i];
        sWhh1[k * G4 + n] = Whh1[i];
    }
    for (int i = tid; i < HDIM * XPAD; i += NTHREADS) {
        h1s[i] = 0.0f;
        h2s[i] = 0.0f;
    }

    float c1[8], c2[8];
#pragma unroll
    for (int q = 0; q < 8; ++q) { c1[q] = 0.0f; c2[q] = 0.0f; }

    const float* xblk = x + (size_t)b0 * (T_STEPS * F_IN);

    for (int t = 0; t < T_STEPS; ++t) {
        // Stream x tile for this timestep, transposed to [k][m]
        for (int i = tid; i < M_TILE * F_IN; i += NTHREADS) {
            int m = i / F_IN, k = i - m * F_IN;
            xsT[k * XPAD + m] = xblk[(size_t)m * (T_STEPS * F_IN) + t * F_IN + k];
        }
        __syncthreads();   // x tile + (first iter: weights, h init) visible; prev h2 writes visible

        u64 acc[4][4];
#pragma unroll
        for (int g = 0; g < 4; ++g)
#pragma unroll
            for (int p = 0; p < 4; ++p) acc[g][p] = 0ULL;

        gemm_part<F_IN>(&xsT[m0], &sWih0[j], acc);   // x_t @ W_ih0^T
        gemm_part<HDIM>(&h1s[m0], &sWhh0[j], acc);   // h1  @ W_hh0^T
        __syncthreads();   // everyone done READING h1s before it is overwritten

        cell_update(acc, c1, &h1s[j * XPAD + m0]);
        __syncthreads();   // new h1 visible

#pragma unroll
        for (int g = 0; g < 4; ++g)
#pragma unroll
            for (int p = 0; p < 4; ++p) acc[g][p] = 0ULL;

        gemm_part<HDIM>(&h1s[m0], &sWih1[j], acc);   // h1_new @ W_ih1^T
        gemm_part<HDIM>(&h2s[m0], &sWhh1[j], acc);   // h2     @ W_hh1^T
        __syncthreads();   // everyone done READING h2s before overwrite

        cell_update(acc, c2, &h2s[j * XPAD + m0]);
        // next iteration's first barrier orders the h2 writes
    }
    __syncthreads();

    // Epilogue: y = relu(c_n @ W1^T + b1) @ W2^T ; c_n = [c1; c2]
    // Stage c into xsT region as cs[(L*64 + m)*33 + j] (conflict-free reads)
    float* cs = xsT;
#pragma unroll
    for (int mp = 0; mp < 4; ++mp) {
        int m = m0 + 2 * mp;
        cs[(m) * 33 + j]          = c1[2 * mp];
        cs[(m + 1) * 33 + j]      = c1[2 * mp + 1];
        cs[(64 + m) * 33 + j]     = c2[2 * mp];
        cs[(64 + m + 1) * 33 + j] = c2[2 * mp + 1];
    }
    __syncthreads();

    if (tid < 2 * M_TILE) {
        int L = tid >> 6;       // layer 0/1
        int m = tid & 63;
        const float* crow = &cs[(L * 64 + m) * 33];
        float y = 0.0f;
#pragma unroll
        for (int u = 0; u < 16; ++u) {
            float s = __ldg(&b1[u]);
#pragma unroll
            for (int q = 0; q < 32; ++q) s += crow[q] * __ldg(&W1[u * 32 + q]);
            y += fmaxf(s, 0.0f) * __ldg(&W2[u]);
        }
        out[L * B_TOTAL + b0 + m] = y;
    }
}

extern "C" void kernel_launch(void* const* d_in, const int* in_sizes, int n_in,
                              void* d_out, int out_size) {
    const float* x    = (const float*)d_in[0];
    const float* Wih0 = (const float*)d_in[1];
    const float* Whh0 = (const float*)d_in[2];
    const float* Wih1 = (const float*)d_in[3];
    const float* Whh1 = (const float*)d_in[4];
    const float* W1   = (const float*)d_in[5];
    const float* b1   = (const float*)d_in[6];
    const float* W2   = (const float*)d_in[7];
    float* out        = (float*)d_out;

    cudaFuncSetAttribute(lstm2_fused_kernel,
                         cudaFuncAttributeMaxDynamicSharedMemorySize, SMEM_BYTES);

    dim3 grid(B_TOTAL / M_TILE);   // 128 CTAs
    dim3 block(NTHREADS);
    lstm2_fused_kernel<<<grid, block, SMEM_BYTES>>>(x, Wih0, Whh0, Wih1, Whh1,
                                                    W1, b1, W2, out);
}

// round 2
// speedup vs baseline: 1.0016x; 1.0016x over previous
#include <cuda_runtime.h>
#include <math.h>

// Problem constants (fixed by the dataset)
#define B_TOTAL 8192
#define T_STEPS 60
#define F_IN    158
#define HDIM    32
#define G4      128          // 4*H gate columns
#define M_TILE  64           // batch rows per CTA
#define NTHREADS 256
#define XPAD    66           // [k][m] row stride for x / h tiles (2-way max write conflict, 8B-aligned pair reads)

// Shared memory layout (in floats)
#define OFF_WIH0 0                       // [158][128] transposed W_ih0
#define OFF_WHH0 (OFF_WIH0 + F_IN*G4)    // 20224 + [32][128]
#define OFF_WIH1 (OFF_WHH0 + HDIM*G4)    // + [32][128]
#define OFF_WHH1 (OFF_WIH1 + HDIM*G4)    // + [32][128]
#define OFF_XT   (OFF_WHH1 + HDIM*G4)    // [158][66] x tile, transposed
#define OFF_H1   (OFF_XT + F_IN*XPAD)    // [32][66]
#define OFF_H2   (OFF_H1 + HDIM*XPAD)    // [32][66]
#define SMEM_FLOATS (OFF_H2 + HDIM*XPAD)
#define SMEM_BYTES  (SMEM_FLOATS * 4)

typedef unsigned long long u64;

__device__ __forceinline__ void ffma2(u64 &acc, u64 a, u64 b) {
    asm("fma.rn.f32x2 %0, %1, %2, %0;" : "+l"(acc) : "l"(a), "l"(b));
}
__device__ __forceinline__ u64 pack2(float x) {
    u64 r; asm("mov.b64 %0, {%1, %1};" : "=l"(r) : "f"(x)); return r;
}
__device__ __forceinline__ float2 unpack2(u64 v) {
    float2 r; asm("mov.b64 {%0, %1}, %2;" : "=f"(r.x), "=f"(r.y) : "l"(v)); return r;
}

__device__ __forceinline__ float sigf(float x) {
    float e = __expf(-x);                       // x<<0 -> e=inf -> result 0 (ok)
    return __fdividef(1.0f, 1.0f + e);
}
__device__ __forceinline__ float tanhf_(float x) {
    float ax = fabsf(x);
    float e = __expf(-2.0f * ax);               // e in (0,1], no overflow path
    float t = __fdividef(1.0f - e, 1.0f + e);
    return copysignf(t, x);
}

// Accumulate gates[j + 32g][m0..m0+7] += sum_k in[k][m] * W[k][col]
// in: [k][m] layout, row stride XPAD; W: [k][128] layout. Lane owns column j (+32g).
template<int K>
__device__ __forceinline__ void gemm_part(const float* __restrict__ xp,
                                          const float* __restrict__ wp,
                                          u64 acc[4][4]) {
#pragma unroll 4
    for (int k = 0; k < K; ++k) {
        u64 a0 = *(const u64*)(xp + 0);
        u64 a1 = *(const u64*)(xp + 2);
        u64 a2 = *(const u64*)(xp + 4);
        u64 a3 = *(const u64*)(xp + 6);
#pragma unroll
        for (int g = 0; g < 4; ++g) {
            u64 wv = pack2(wp[g * 32]);
            ffma2(acc[g][0], a0, wv);
            ffma2(acc[g][1], a1, wv);
            ffma2(acc[g][2], a2, wv);
            ffma2(acc[g][3], a3, wv);
        }
        xp += XPAD;
        wp += G4;
    }
}

// Pointwise LSTM cell for 8 batch rows of hidden unit j; writes new h to smem row.
__device__ __forceinline__ void cell_update(u64 acc[4][4], float c[8], float* __restrict__ hrow) {
#pragma unroll
    for (int mp = 0; mp < 4; ++mp) {
        float2 iv = unpack2(acc[0][mp]);
        float2 fv = unpack2(acc[1][mp]);
        float2 gv = unpack2(acc[2][mp]);
        float2 ov = unpack2(acc[3][mp]);
        float c0 = sigf(fv.x) * c[2 * mp]     + sigf(iv.x) * tanhf_(gv.x);
        float c1 = sigf(fv.y) * c[2 * mp + 1] + sigf(iv.y) * tanhf_(gv.y);
        c[2 * mp]     = c0;
        c[2 * mp + 1] = c1;
        float2 hv;
        hv.x = sigf(ov.x) * tanhf_(c0);
        hv.y = sigf(ov.y) * tanhf_(c1);
        *(float2*)(hrow + 2 * mp) = hv;
    }
}

__global__ void __launch_bounds__(NTHREADS)
lstm2_fused_kernel(const float* __restrict__ x,
                   const float* __restrict__ Wih0,
                   const float* __restrict__ Whh0,
                   const float* __restrict__ Wih1,
                   const float* __restrict__ Whh1,
                   const float* __restrict__ W1,
                   const float* __restrict__ b1,
                   const float* __restrict__ W2,
                   float* __restrict__ out) {
    extern __shared__ float sm[];
    float* sWih0 = sm + OFF_WIH0;
    float* sWhh0 = sm + OFF_WHH0;
    float* sWih1 = sm + OFF_WIH1;
    float* sWhh1 = sm + OFF_WHH1;
    float* xsT   = sm + OFF_XT;
    float* h1s   = sm + OFF_H1;
    float* h2s   = sm + OFF_H2;

    const int tid = threadIdx.x;
    const int j   = tid & 31;        // hidden unit / gate column owned by this lane
    const int wrp = tid >> 5;        // warp id -> batch sub-tile
    const int m0  = wrp * 8;
    const int b0  = blockIdx.x * M_TILE;

    // Load & transpose weights into SMEM: s[k][n] = W[n][k]
    for (int i = tid; i < G4 * F_IN; i += NTHREADS) {
        int n = i / F_IN, k = i - n * F_IN;
        sWih0[k * G4 + n] = Wih0[i];
    }
    for (int i = tid; i < G4 * HDIM; i += NTHREADS) {
        int n = i >> 5, k = i & 31;
        sWhh0[k * G4 + n] = Whh0[i];
        sWih1[k * G4 + n] = Wih1[i];
        sWhh1[k * G4 + n] = Whh1[i];
    }
    for (int i = tid; i < HDIM * XPAD; i += NTHREADS) {
        h1s[i] = 0.0f;
        h2s[i] = 0.0f;
    }

    float c1[8], c2[8];
#pragma unroll
    for (int q = 0; q < 8; ++q) { c1[q] = 0.0f; c2[q] = 0.0f; }

    const float* xblk = x + (size_t)b0 * (T_STEPS * F_IN);

    for (int t = 0; t < T_STEPS; ++t) {
        // Stream x tile for this timestep, transposed to [k][m]
        for (int i = tid; i < M_TILE * F_IN; i += NTHREADS) {
            int m = i / F_IN, k = i - m * F_IN;
            xsT[k * XPAD + m] = xblk[(size_t)m * (T_STEPS * F_IN) + t * F_IN + k];
        }
        __syncthreads();   // x tile + (first iter: weights, h init) visible; prev h2 writes visible

        u64 acc[4][4];
#pragma unroll
        for (int g = 0; g < 4; ++g)
#pragma unroll
            for (int p = 0; p < 4; ++p) acc[g][p] = 0ULL;

        gemm_part<F_IN>(&xsT[m0], &sWih0[j], acc);   // x_t @ W_ih0^T
        gemm_part<HDIM>(&h1s[m0], &sWhh0[j], acc);   // h1  @ W_hh0^T
        __syncthreads();   // everyone done READING h1s before it is overwritten

        cell_update(acc, c1, &h1s[j * XPAD + m0]);
        __syncthreads();   // new h1 visible

#pragma unroll
        for (int g = 0; g < 4; ++g)
#pragma unroll
            for (int p = 0; p < 4; ++p) acc[g][p] = 0ULL;

        gemm_part<HDIM>(&h1s[m0], &sWih1[j], acc);   // h1_new @ W_ih1^T
        gemm_part<HDIM>(&h2s[m0], &sWhh1[j], acc);   // h2     @ W_hh1^T
        __syncthreads();   // everyone done READING h2s before overwrite

        cell_update(acc, c2, &h2s[j * XPAD + m0]);
        // next iteration's first barrier orders the h2 writes
    }
    __syncthreads();

    // Epilogue: y = relu(c_n @ W1^T + b1) @ W2^T ; c_n = [c1; c2]
    // Stage c into xsT region as cs[(L*64 + m)*33 + j] (conflict-free reads)
    float* cs = xsT;
#pragma unroll
    for (int mp = 0; mp < 4; ++mp) {
        int m = m0 + 2 * mp;
        cs[(m) * 33 + j]          = c1[2 * mp];
        cs[(m + 1) * 33 + j]      = c1[2 * mp + 1];
        cs[(64 + m) * 33 + j]     = c2[2 * mp];
        cs[(64 + m + 1) * 33 + j] = c2[2 * mp + 1];
    }
    __syncthreads();

    if (tid < 2 * M_TILE) {
        int L = tid >> 6;       // layer 0/1
        int m = tid & 63;
        const float* crow = &cs[(L * 64 + m) * 33];
        float y = 0.0f;
#pragma unroll
        for (int u = 0; u < 16; ++u) {
            float s = __ldg(&b1[u]);
#pragma unroll
            for (int q = 0; q < 32; ++q) s += crow[q] * __ldg(&W1[u * 32 + q]);
            y += fmaxf(s, 0.0f) * __ldg(&W2[u]);
        }
        out[L * B_TOTAL + b0 + m] = y;
    }
}

extern "C" void kernel_launch(void* const* d_in, const int* in_sizes, int n_in,
                              void* d_out, int out_size) {
    const float* x    = (const float*)d_in[0];
    const float* Wih0 = (const float*)d_in[1];
    const float* Whh0 = (const float*)d_in[2];
    const float* Wih1 = (const float*)d_in[3];
    const float* Whh1 = (const float*)d_in[4];
    const float* W1   = (const float*)d_in[5];
    const float* b1   = (const float*)d_in[6];
    const float* W2   = (const float*)d_in[7];
    float* out        = (float*)d_out;

    cudaFuncSetAttribute(lstm2_fused_kernel,
                         cudaFuncAttributeMaxDynamicSharedMemorySize, SMEM_BYTES);

    dim3 grid(B_TOTAL / M_TILE);   // 128 CTAs
    dim3 block(NTHREADS);
    lstm2_fused_kernel<<<grid, block, SMEM_BYTES>>>(x, Wih0, Whh0, Wih1, Whh1,
                                                    W1, b1, W2, out);
}

// round 4
// speedup vs baseline: 1.3488x; 1.3467x over previous
#include <cuda_runtime.h>
#include <stdint.h>
#include <math.h>

// Problem constants
#define B_TOTAL 8192
#define T_STEPS 60
#define F_IN    158
#define HDIM    32
#define G4      128
#define M_TILE  64
#define NBLK    (B_TOTAL / M_TILE)      // 128
#define NTILES  (T_STEPS * NBLK)        // 7680
#define XPAD    66
#define SP      (HDIM * XPAD)           // 2112 floats per h buffer
#define TILE_FLOATS (G4 * XPAD)         // 8448 floats per xg tile
#define TILE_BYTES  (TILE_FLOATS * 4)   // 33792 B (16B multiple)

typedef unsigned long long u64;

// ---- 260 MB device scratch for the precomputed input projection ----
// layout: g_xg[(t*NBLK + blk)][col(128)][m(66 padded)], only m<64 valid
__device__ __align__(256) float g_xg[(size_t)NTILES * TILE_FLOATS];

// ---------------- helpers ----------------
__device__ __forceinline__ void ffma2(u64 &acc, u64 a, u64 b) {
    asm("fma.rn.f32x2 %0, %1, %2, %0;" : "+l"(acc) : "l"(a), "l"(b));
}
__device__ __forceinline__ u64 pack2(float x) {
    u64 r; asm("mov.b64 %0, {%1, %1};" : "=l"(r) : "f"(x)); return r;
}
__device__ __forceinline__ float2 unpack2(u64 v) {
    float2 r; asm("mov.b64 {%0, %1}, %2;" : "=f"(r.x), "=f"(r.y) : "l"(v)); return r;
}
__device__ __forceinline__ float sigf(float x) {
    float e = __expf(-x);
    return __fdividef(1.0f, 1.0f + e);
}
__device__ __forceinline__ float tanhf_(float x) {
    float ax = fabsf(x);
    float e = __expf(-2.0f * ax);
    float t = __fdividef(1.0f - e, 1.0f + e);
    return copysignf(t, x);
}
__device__ __forceinline__ void cp_async4(uint32_t dst, const void* src) {
    asm volatile("cp.async.ca.shared.global [%0], [%1], 4;" :: "r"(dst), "l"(src));
}
__device__ __forceinline__ void cp_async16(uint32_t dst, const void* src) {
    asm volatile("cp.async.cg.shared.global [%0], [%1], 16;" :: "r"(dst), "l"(src));
}
__device__ __forceinline__ void cp_commit() { asm volatile("cp.async.commit_group;"); }
__device__ __forceinline__ void cp_wait1()  { asm volatile("cp.async.wait_group 1;" ::: "memory"); }

// gates[j+32g][m0..m0+7] += sum_k in[k][m] * W[k][col]; in stride XPAD, W stride G4
template<int K>
__device__ __forceinline__ void gemm8(const float* __restrict__ xp,
                                      const float* __restrict__ wp,
                                      u64 acc[4][4]) {
#pragma unroll 4
    for (int k = 0; k < K; ++k) {
        u64 a0 = *(const u64*)(xp + 0);
        u64 a1 = *(const u64*)(xp + 2);
        u64 a2 = *(const u64*)(xp + 4);
        u64 a3 = *(const u64*)(xp + 6);
#pragma unroll
        for (int g = 0; g < 4; ++g) {
            u64 wv = pack2(wp[g * 32]);
            ffma2(acc[g][0], a0, wv);
            ffma2(acc[g][1], a1, wv);
            ffma2(acc[g][2], a2, wv);
            ffma2(acc[g][3], a3, wv);
        }
        xp += XPAD;
        wp += G4;
    }
}

// 4-row variant for the recurrent kernel (16 warps x 4 rows)
template<int K>
__device__ __forceinline__ void gemm4(const float* __restrict__ xp,
                                      const float* __restrict__ wp,
                                      u64 acc[4][2]) {
#pragma unroll
    for (int k = 0; k < K; ++k) {
        u64 a0 = *(const u64*)(xp + 0);
        u64 a1 = *(const u64*)(xp + 2);
#pragma unroll
        for (int g = 0; g < 4; ++g) {
            u64 wv = pack2(wp[g * 32]);
            ffma2(acc[g][0], a0, wv);
            ffma2(acc[g][1], a1, wv);
        }
        xp += XPAD;
        wp += G4;
    }
}

__device__ __forceinline__ void cell4(u64 acc[4][2], float c[4], float* __restrict__ hrow) {
#pragma unroll
    for (int p = 0; p < 2; ++p) {
        float2 iv = unpack2(acc[0][p]);
        float2 fv = unpack2(acc[1][p]);
        float2 gv = unpack2(acc[2][p]);
        float2 ov = unpack2(acc[3][p]);
        float c0 = sigf(fv.x) * c[2 * p]     + sigf(iv.x) * tanhf_(gv.x);
        float c1 = sigf(fv.y) * c[2 * p + 1] + sigf(iv.y) * tanhf_(gv.y);
        c[2 * p]     = c0;
        c[2 * p + 1] = c1;
        float2 hv;
        hv.x = sigf(ov.x) * tanhf_(c0);
        hv.y = sigf(ov.y) * tanhf_(c1);
        *(float2*)(hrow + 2 * p) = hv;
    }
}

// =======================================================================
// Kernel A: xg[t][blk][col][m] = (x_t(blk) @ W_ih0^T), persistent grid
// =======================================================================
#define A_THREADS 256
#define A_SMEM_FLOATS (F_IN*G4 + 2*F_IN*XPAD + TILE_FLOATS)
#define A_SMEM_BYTES  (A_SMEM_FLOATS * 4)   // 198112 B

__global__ void __launch_bounds__(A_THREADS)
xg_kernel(const float* __restrict__ x, const float* __restrict__ Wih0) {
    extern __shared__ float sm[];
    float* sW   = sm;                         // [158][128]
    float* xb   = sm + F_IN * G4;             // [2][158][66]
    float* outb = xb + 2 * F_IN * XPAD;       // [128][66]

    const int tid = threadIdx.x;
    const int j = tid & 31, wrp = tid >> 5, m0 = wrp * 8;

    for (int i = tid; i < G4 * F_IN; i += A_THREADS) {
        int n = i / F_IN, k = i - n * F_IN;
        sW[k * G4 + n] = Wih0[i];
    }

    int tile = blockIdx.x;
    // prologue prefetch of first tile into buffer 0
    {
        int t = tile / NBLK, blk = tile - t * NBLK;
        const float* xsrc = x + (size_t)blk * M_TILE * (T_STEPS * F_IN) + (size_t)t * F_IN;
        for (int i = tid; i < M_TILE * F_IN; i += A_THREADS) {
            int m = i / F_IN, k = i - m * F_IN;
            cp_async4((uint32_t)__cvta_generic_to_shared(xb + k * XPAD + m),
                      xsrc + (size_t)m * (T_STEPS * F_IN) + k);
        }
    }
    cp_commit();

    int cur = 0;
    for (; tile < NTILES; tile += gridDim.x) {
        int nt = tile + gridDim.x;
        if (nt < NTILES) {
            int t = nt / NBLK, blk = nt - t * NBLK;
            const float* xsrc = x + (size_t)blk * M_TILE * (T_STEPS * F_IN) + (size_t)t * F_IN;
            float* dst = xb + (cur ^ 1) * (F_IN * XPAD);
            for (int i = tid; i < M_TILE * F_IN; i += A_THREADS) {
                int m = i / F_IN, k = i - m * F_IN;
                cp_async4((uint32_t)__cvta_generic_to_shared(dst + k * XPAD + m),
                          xsrc + (size_t)m * (T_STEPS * F_IN) + k);
            }
        }
        cp_commit();
        cp_wait1();               // current tile's x resident
        __syncthreads();          // visible to all; also orders prev outb reads

        u64 acc[4][4];
#pragma unroll
        for (int g = 0; g < 4; ++g)
#pragma unroll
            for (int p = 0; p < 4; ++p) acc[g][p] = 0ULL;

        gemm8<F_IN>(xb + cur * (F_IN * XPAD) + m0, sW + j, acc);

        // stage output tile (reg -> smem, 2-way max conflict)
#pragma unroll
        for (int g = 0; g < 4; ++g)
#pragma unroll
            for (int p = 0; p < 4; ++p)
                *(u64*)(outb + (j + 32 * g) * XPAD + m0 + 2 * p) = acc[g][p];
        __syncthreads();

        // coalesced float4 store of the whole padded tile
        float4* dstg = (float4*)(g_xg + (size_t)tile * TILE_FLOATS);
        const float4* srcv = (const float4*)outb;
        for (int i = tid; i < TILE_FLOATS / 4; i += A_THREADS) dstg[i] = srcv[i];

        cur ^= 1;
    }
}

// =======================================================================
// Kernel B: recurrent part, gates seeded from g_xg, K=32 hidden gemms
// =======================================================================
#define B_THREADS 512
#define B_SMEM_FLOATS (3*HDIM*G4 + 4*SP + 2*TILE_FLOATS)
#define B_SMEM_BYTES  (B_SMEM_FLOATS * 4)   // 150528 B

__global__ void __launch_bounds__(B_THREADS)
lstm_rec_kernel(const float* __restrict__ Whh0, const float* __restrict__ Wih1,
                const float* __restrict__ Whh1, const float* __restrict__ W1,
                const float* __restrict__ b1,   const float* __restrict__ W2,
                float* __restrict__ out) {
    extern __shared__ float sm[];
    float* sWhh0 = sm;                        // [32][128]
    float* sWih1 = sm + HDIM * G4;
    float* sWhh1 = sm + 2 * HDIM * G4;
    float* hbuf  = sm + 3 * HDIM * G4;        // h1[2], h2[2] each SP floats
    float* xgb   = hbuf + 4 * SP;             // [2][8448]

    const int tid = threadIdx.x;
    const int j = tid & 31, wrp = tid >> 5, m0 = wrp * 4;   // 16 warps x 4 rows
    const int blk = blockIdx.x;

    for (int i = tid; i < G4 * HDIM; i += B_THREADS) {
        int n = i >> 5, k = i & 31;
        sWhh0[k * G4 + n] = Whh0[i];
        sWih1[k * G4 + n] = Wih1[i];
        sWhh1[k * G4 + n] = Whh1[i];
    }
    for (int i = tid; i < 4 * SP; i += B_THREADS) hbuf[i] = 0.0f;

    float c1[4] = {0.f, 0.f, 0.f, 0.f};
    float c2[4] = {0.f, 0.f, 0.f, 0.f};

    // prologue: prefetch xg tile for t=0 into buffer 0
    {
        const float4* src = (const float4*)(g_xg + (size_t)blk * TILE_FLOATS);
        for (int i = tid; i < TILE_FLOATS / 4; i += B_THREADS)
            cp_async16((uint32_t)__cvta_generic_to_shared(xgb + i * 4), src + i);
    }
    cp_commit();

    for (int t = 0; t < T_STEPS; ++t) {
        const int cb = t & 1;       // xg buffer parity
        const int hp = t & 1;       // h state entering step t lives in [hp]

        if (t + 1 < T_STEPS) {
            const float4* src = (const float4*)(g_xg + (size_t)((t + 1) * NBLK + blk) * TILE_FLOATS);
            float* dst = xgb + (cb ^ 1) * TILE_FLOATS;
            for (int i = tid; i < TILE_FLOATS / 4; i += B_THREADS)
                cp_async16((uint32_t)__cvta_generic_to_shared(dst + i * 4), src + i);
        }
        cp_commit();
        cp_wait1();
        __syncthreads();            // [A] xg ready; prev-step h writes visible

        // ---- layer 1: gates = xg + h1 @ Whh0^T ----
        const float* xg0 = xgb + cb * TILE_FLOATS;
        u64 acc[4][2];
#pragma unroll
        for (int g = 0; g < 4; ++g)
#pragma unroll
            for (int p = 0; p < 2; ++p)
                acc[g][p] = *(const u64*)(xg0 + (j + 32 * g) * XPAD + m0 + 2 * p);

        gemm4<HDIM>(hbuf + hp * SP + m0, sWhh0 + j, acc);
        cell4(acc, c1, hbuf + (hp ^ 1) * SP + j * XPAD + m0);
        __syncthreads();            // [B] new h1 visible

        // ---- layer 2: gates = h1_new @ Wih1^T + h2 @ Whh1^T ----
#pragma unroll
        for (int g = 0; g < 4; ++g)
#pragma unroll
            for (int p = 0; p < 2; ++p) acc[g][p] = 0ULL;

        gemm4<HDIM>(hbuf + (hp ^ 1) * SP + m0, sWih1 + j, acc);
        gemm4<HDIM>(hbuf + (2 + hp) * SP + m0, sWhh1 + j, acc);
        cell4(acc, c2, hbuf + (2 + (hp ^ 1)) * SP + j * XPAD + m0);
        // next step's [A] orders the h2 writes
    }
    __syncthreads();

    // ---- epilogue: y = relu(c_n @ W1^T + b1) @ W2^T ----
    float* cs = xgb;                // reuse; [128 rows][33]
#pragma unroll
    for (int q = 0; q < 4; ++q) {
        cs[(m0 + q) * 33 + j]      = c1[q];
        cs[(64 + m0 + q) * 33 + j] = c2[q];
    }
    __syncthreads();

    if (tid < 2 * M_TILE) {
        int L = tid >> 6, m = tid & 63;
        const float* crow = &cs[(L * 64 + m) * 33];
        float y = 0.0f;
#pragma unroll
        for (int u = 0; u < 16; ++u) {
            float s = __ldg(&b1[u]);
#pragma unroll
            for (int q = 0; q < 32; ++q) s += crow[q] * __ldg(&W1[u * 32 + q]);
            y += fmaxf(s, 0.0f) * __ldg(&W2[u]);
        }
        out[L * B_TOTAL + blk * M_TILE + m] = y;
    }
}

extern "C" void kernel_launch(void* const* d_in, const int* in_sizes, int n_in,
                              void* d_out, int out_size) {
    const float* x    = (const float*)d_in[0];
    const float* Wih0 = (const float*)d_in[1];
    const float* Whh0 = (const float*)d_in[2];
    const float* Wih1 = (const float*)d_in[3];
    const float* Whh1 = (const float*)d_in[4];
    const float* W1   = (const float*)d_in[5];
    const float* b1   = (const float*)d_in[6];
    const float* W2   = (const float*)d_in[7];
    float* out        = (float*)d_out;

    cudaFuncSetAttribute(xg_kernel, cudaFuncAttributeMaxDynamicSharedMemorySize, A_SMEM_BYTES);
    cudaFuncSetAttribute(lstm_rec_kernel, cudaFuncAttributeMaxDynamicSharedMemorySize, B_SMEM_BYTES);

    int dev = 0;
    cudaGetDevice(&dev);
    int sms = 148;
    cudaDeviceGetAttribute(&sms, cudaDevAttrMultiProcessorCount, dev);
    if (sms < 1) sms = 148;
    if (sms > NTILES) sms = NTILES;

    xg_kernel<<<sms, A_THREADS, A_SMEM_BYTES>>>(x, Wih0);
    lstm_rec_kernel<<<NBLK, B_THREADS, B_SMEM_BYTES>>>(Whh0, Wih1, Whh1, W1, b1, W2, out);
}

// round 5
// speedup vs baseline: 1.4533x; 1.0774x over previous
#include <cuda_runtime.h>
#include <stdint.h>
#include <math.h>

// Problem constants
#define B_TOTAL 8192
#define T_STEPS 60
#define F_IN    158
#define HDIM    32
#define G4      128
#define M_TILE  64
#define NBLK    (B_TOTAL / M_TILE)      // 128
#define NTILES  (T_STEPS * NBLK)        // 7680
#define KP      79                      // k-pairs covering F_IN=158 exactly

typedef unsigned long long u64;

// 251.7 MB scratch: xg[tile][m(64)][n(128)], tile = t*NBLK + blk
__device__ __align__(256) float g_xg[(size_t)NTILES * M_TILE * G4];

// ---------------- helpers ----------------
__device__ __forceinline__ void ffma2(u64 &acc, u64 a, u64 b) {
    asm("fma.rn.f32x2 %0, %1, %2, %0;" : "+l"(acc) : "l"(a), "l"(b));
}
__device__ __forceinline__ u64 pack2(float x, float y) {
    u64 r; asm("mov.b64 %0, {%1, %2};" : "=l"(r) : "f"(x), "f"(y)); return r;
}
__device__ __forceinline__ float2 unpack2(u64 v) {
    float2 r; asm("mov.b64 {%0, %1}, %2;" : "=f"(r.x), "=f"(r.y) : "l"(v)); return r;
}
__device__ __forceinline__ float sigf(float x) {
    float e = __expf(-x);
    return __fdividef(1.0f, 1.0f + e);
}
__device__ __forceinline__ float tanhf_(float x) {
    float ax = fabsf(x);
    float e = __expf(-2.0f * ax);
    float t = __fdividef(1.0f - e, 1.0f + e);
    return copysignf(t, x);
}
__device__ __forceinline__ void cp_async8(uint32_t dst, const void* src) {
    asm volatile("cp.async.ca.shared.global [%0], [%1], 8;" :: "r"(dst), "l"(src));
}
__device__ __forceinline__ void cp_async16(uint32_t dst, const void* src) {
    asm volatile("cp.async.cg.shared.global [%0], [%1], 16;" :: "r"(dst), "l"(src));
}
__device__ __forceinline__ void cp_commit() { asm volatile("cp.async.commit_group;"); }
__device__ __forceinline__ void cp_wait1()  { asm volatile("cp.async.wait_group 1;" ::: "memory"); }

// =======================================================================
// Kernel A: xg[tile][m][n] = x_tile @ W_ih0^T
//   k-pair split accumulators: acc = (sum_{even k}, sum_{odd k}), fold at end.
//   x tile in smem as [m][k] (row stride 160 floats), loaded via cp.async16.
//   Weights interleaved in smem: sWp[kp][n] = (W[n][2kp], W[n][2kp+1]).
// =======================================================================
#define A_THREADS 256
#define A_XROW    160                       // floats per x smem row (640 B)
#define A_XBUF    (M_TILE * A_XROW)         // 10240 floats per buffer
#define A_SW_FLOATS (2 * KP * G4)           // 20224 floats (10112 u64)
#define A_SMEM_FLOATS (A_SW_FLOATS + 2*A_XBUF + M_TILE*G4)
#define A_SMEM_BYTES  (A_SMEM_FLOATS * 4)   // 195584 B

__device__ __forceinline__ void a_copy_tile(const float* __restrict__ x,
                                            int tile, float* xbuf, int tid) {
    int t = tile >> 7;             // tile / NBLK
    int blk = tile & (NBLK - 1);
    const char* srcbase = (const char*)x + (size_t)(blk * M_TILE) * (T_STEPS * F_IN * 4)
                                          + (size_t)t * (F_IN * 4);
    uint32_t dstbase = (uint32_t)__cvta_generic_to_shared(xbuf);
    int mis = t & 1;               // src rows 16B-aligned iff t even
    // 40 chunks per row x 64 rows = 2560 ops
    for (int i = tid; i < M_TILE * 40; i += A_THREADS) {
        int row = i / 40, c = i - row * 40;
        const char* s = srcbase + (size_t)row * (T_STEPS * F_IN * 4);
        uint32_t d = dstbase + row * (A_XROW * 4);
        if (!mis) {
            if (c == 0) cp_async8(d + 624, s + 624);
            else        cp_async16(d + 16 * (c - 1), s + 16 * (c - 1));
        } else {
            if (c == 0) cp_async8(d + 8, s);
            else        cp_async16(d + 16 * c, s + 8 + 16 * (c - 1));
        }
    }
}

__global__ void __launch_bounds__(A_THREADS)
xg_kernel(const float* __restrict__ x, const float* __restrict__ Wih0) {
    extern __shared__ float sm[];
    u64*   sWp  = (u64*)sm;                      // [KP][128] interleaved k-pairs
    float* xb   = sm + A_SW_FLOATS;              // 2 x [64][160]
    float* outb = xb + 2 * A_XBUF;               // [64][128]

    const int tid = threadIdx.x;
    const int lane = tid & 31, wrp = tid >> 5;
    const int m0 = wrp * 8;

    // interleaved weights: sWp[kp*128 + n] = (W[n][2kp], W[n][2kp+1])
    for (int i = tid; i < KP * G4; i += A_THREADS) {
        int n = i / KP, kp = i - n * KP;
        sWp[kp * G4 + n] = *(const u64*)(Wih0 + n * F_IN + 2 * kp);
    }

    int tile = blockIdx.x;
    a_copy_tile(x, tile, xb, tid);
    cp_commit();

    int cur = 0;
    for (; tile < NTILES; tile += gridDim.x) {
        int nt = tile + gridDim.x;
        if (nt < NTILES) a_copy_tile(x, nt, xb + (cur ^ 1) * A_XBUF, tid);
        cp_commit();
        cp_wait1();
        __syncthreads();          // x tile + weights resident; outb drained

        const int sh = (tile >> 7) & 1;   // 2-float shift for misaligned tiles
        const float* xbase = xb + cur * A_XBUF + m0 * A_XROW + 2 * sh;

        u64 acc[8][4];
#pragma unroll
        for (int q = 0; q < 8; ++q)
#pragma unroll
            for (int g = 0; g < 4; ++g) acc[q][g] = 0ULL;

#pragma unroll 2
        for (int kp = 0; kp < KP; ++kp) {
            u64 xq[8];
#pragma unroll
            for (int q = 0; q < 8; ++q)
                xq[q] = *(const u64*)(xbase + q * A_XROW + 2 * kp);
            u64 wv[4];
#pragma unroll
            for (int g = 0; g < 4; ++g)
                wv[g] = sWp[kp * G4 + lane + 32 * g];
#pragma unroll
            for (int q = 0; q < 8; ++q)
#pragma unroll
                for (int g = 0; g < 4; ++g)
                    ffma2(acc[q][g], xq[q], wv[g]);
        }

        // fold k-split halves, stage to outb[m][n]
#pragma unroll
        for (int q = 0; q < 8; ++q)
#pragma unroll
            for (int g = 0; g < 4; ++g) {
                float2 v = unpack2(acc[q][g]);
                outb[(m0 + q) * G4 + lane + 32 * g] = v.x + v.y;
            }
        __syncthreads();

        // coalesced STG.128 of the whole tile
        float4* dstg = (float4*)(g_xg + (size_t)tile * (M_TILE * G4));
        const float4* srcv = (const float4*)outb;
        for (int i = tid; i < (M_TILE * G4) / 4; i += A_THREADS) dstg[i] = srcv[i];

        cur ^= 1;
    }
}

// =======================================================================
// Kernel B: recurrence. Warp-local h (no __syncthreads in the loop),
// dup'd f32x2 weights in smem, xg streamed from gmem with coalesced LDG.
// =======================================================================
#define B_THREADS 256
#define HPAD 66
#define B_SW  (HDIM * G4 * 2)               // floats per dup'd weight matrix (8192)
#define B_SMEM_FLOATS (3 * B_SW + 2 * HDIM * HPAD)
#define B_SMEM_BYTES  (B_SMEM_FLOATS * 4)   // 115200 B

__global__ void __launch_bounds__(B_THREADS)
lstm_rec_kernel(const float* __restrict__ Whh0, const float* __restrict__ Wih1,
                const float* __restrict__ Whh1, const float* __restrict__ W1,
                const float* __restrict__ b1,   const float* __restrict__ W2,
                float* __restrict__ out) {
    extern __shared__ float sm[];
    u64* sW0 = (u64*)sm;                       // Whh0 dup'd [k][128]
    u64* sW1 = (u64*)(sm + B_SW);              // Wih1
    u64* sW2 = (u64*)(sm + 2 * B_SW);          // Whh1
    float* h1 = sm + 3 * B_SW;                 // [32][66]
    float* h2 = h1 + HDIM * HPAD;

    const int tid = threadIdx.x;
    const int j = tid & 31, wrp = tid >> 5;
    const int m0 = wrp * 8;                    // 8 warps x 8 rows = 64
    const int blk = blockIdx.x;

    for (int i = tid; i < HDIM * G4; i += B_THREADS) {
        int n = i >> 5, k = i & 31;
        float w0 = Whh0[n * HDIM + k];
        float w1 = Wih1[n * HDIM + k];
        float w2 = Whh1[n * HDIM + k];
        sW0[k * G4 + n] = pack2(w0, w0);
        sW1[k * G4 + n] = pack2(w1, w1);
        sW2[k * G4 + n] = pack2(w2, w2);
    }
    for (int i = tid; i < 2 * HDIM * HPAD; i += B_THREADS) h1[i] = 0.0f;
    __syncthreads();

    float c1[8], c2[8];
#pragma unroll
    for (int q = 0; q < 8; ++q) { c1[q] = 0.0f; c2[q] = 0.0f; }

    for (int t = 0; t < T_STEPS; ++t) {
        // prefetch xg for this step (coalesced; consumed after the K=32 gemm)
        const float* xt = g_xg + ((size_t)t * NBLK + blk) * (M_TILE * G4);
        float xr[32];
#pragma unroll
        for (int g = 0; g < 4; ++g)
#pragma unroll
            for (int q = 0; q < 8; ++q)
                xr[g * 8 + q] = __ldg(xt + (m0 + q) * G4 + j + 32 * g);

        // ---- layer 1: acc = h1 @ Whh0^T  (gates += xg later) ----
        u64 acc[4][4];
#pragma unroll
        for (int g = 0; g < 4; ++g)
#pragma unroll
            for (int p = 0; p < 4; ++p) acc[g][p] = 0ULL;

#pragma unroll 4
        for (int k = 0; k < HDIM; ++k) {
            u64 hp[4];
#pragma unroll
            for (int p = 0; p < 4; ++p)
                hp[p] = *(const u64*)(h1 + k * HPAD + m0 + 2 * p);
            u64 wv[4];
#pragma unroll
            for (int g = 0; g < 4; ++g) wv[g] = sW0[k * G4 + j + 32 * g];
#pragma unroll
            for (int g = 0; g < 4; ++g)
#pragma unroll
                for (int p = 0; p < 4; ++p) ffma2(acc[g][p], hp[p], wv[g]);
        }

        float hn[8];
#pragma unroll
        for (int p = 0; p < 4; ++p) {
            float2 iv = unpack2(acc[0][p]);
            float2 fv = unpack2(acc[1][p]);
            float2 gv = unpack2(acc[2][p]);
            float2 ov = unpack2(acc[3][p]);
            iv.x += xr[2 * p];      iv.y += xr[2 * p + 1];
            fv.x += xr[8 + 2 * p];  fv.y += xr[8 + 2 * p + 1];
            gv.x += xr[16 + 2 * p]; gv.y += xr[16 + 2 * p + 1];
            ov.x += xr[24 + 2 * p]; ov.y += xr[24 + 2 * p + 1];
            float ca = sigf(fv.x) * c1[2 * p]     + sigf(iv.x) * tanhf_(gv.x);
            float cb = sigf(fv.y) * c1[2 * p + 1] + sigf(iv.y) * tanhf_(gv.y);
            c1[2 * p] = ca; c1[2 * p + 1] = cb;
            hn[2 * p]     = sigf(ov.x) * tanhf_(ca);
            hn[2 * p + 1] = sigf(ov.y) * tanhf_(cb);
        }
        __syncwarp();               // all lanes done reading old h1
#pragma unroll
        for (int p = 0; p < 4; ++p)
            *(float2*)(h1 + j * HPAD + m0 + 2 * p) = make_float2(hn[2 * p], hn[2 * p + 1]);
        __syncwarp();               // new h1 visible warp-wide

        // ---- layer 2: acc = h1_new @ Wih1^T + h2 @ Whh1^T ----
#pragma unroll
        for (int g = 0; g < 4; ++g)
#pragma unroll
            for (int p = 0; p < 4; ++p) acc[g][p] = 0ULL;

#pragma unroll 4
        for (int k = 0; k < HDIM; ++k) {
            u64 ha[4], hb[4];
#pragma unroll
            for (int p = 0; p < 4; ++p) {
                ha[p] = *(const u64*)(h1 + k * HPAD + m0 + 2 * p);
                hb[p] = *(const u64*)(h2 + k * HPAD + m0 + 2 * p);
            }
            u64 wa[4], wb[4];
#pragma unroll
            for (int g = 0; g < 4; ++g) {
                wa[g] = sW1[k * G4 + j + 32 * g];
                wb[g] = sW2[k * G4 + j + 32 * g];
            }
#pragma unroll
            for (int g = 0; g < 4; ++g)
#pragma unroll
                for (int p = 0; p < 4; ++p) {
                    ffma2(acc[g][p], ha[p], wa[g]);
                    ffma2(acc[g][p], hb[p], wb[g]);
                }
        }

#pragma unroll
        for (int p = 0; p < 4; ++p) {
            float2 iv = unpack2(acc[0][p]);
            float2 fv = unpack2(acc[1][p]);
            float2 gv = unpack2(acc[2][p]);
            float2 ov = unpack2(acc[3][p]);
            float ca = sigf(fv.x) * c2[2 * p]     + sigf(iv.x) * tanhf_(gv.x);
            float cb = sigf(fv.y) * c2[2 * p + 1] + sigf(iv.y) * tanhf_(gv.y);
            c2[2 * p] = ca; c2[2 * p + 1] = cb;
            hn[2 * p]     = sigf(ov.x) * tanhf_(ca);
            hn[2 * p + 1] = sigf(ov.y) * tanhf_(cb);
        }
        __syncwarp();               // all lanes done reading old h2
#pragma unroll
        for (int p = 0; p < 4; ++p)
            *(float2*)(h2 + j * HPAD + m0 + 2 * p) = make_float2(hn[2 * p], hn[2 * p + 1]);
        __syncwarp();
    }
    __syncthreads();

    // ---- epilogue: y = relu(c_n @ W1^T + b1) @ W2^T ----
    float* cs = sm;                 // reuse weight region: [128 rows][33]
#pragma unroll
    for (int q = 0; q < 8; ++q) {
        cs[(m0 + q) * 33 + j]      = c1[q];
        cs[(64 + m0 + q) * 33 + j] = c2[q];
    }
    __syncthreads();

    if (tid < 2 * M_TILE) {
        int L = tid >> 6, m = tid & 63;
        const float* crow = &cs[(L * 64 + m) * 33];
        float y = 0.0f;
#pragma unroll
        for (int u = 0; u < 16; ++u) {
            float s = __ldg(&b1[u]);
#pragma unroll
            for (int q = 0; q < 32; ++q) s += crow[q] * __ldg(&W1[u * 32 + q]);
            y += fmaxf(s, 0.0f) * __ldg(&W2[u]);
        }
        out[L * B_TOTAL + blk * M_TILE + m] = y;
    }
}

extern "C" void kernel_launch(void* const* d_in, const int* in_sizes, int n_in,
                              void* d_out, int out_size) {
    const float* x    = (const float*)d_in[0];
    const float* Wih0 = (const float*)d_in[1];
    const float* Whh0 = (const float*)d_in[2];
    const float* Wih1 = (const float*)d_in[3];
    const float* Whh1 = (const float*)d_in[4];
    const float* W1   = (const float*)d_in[5];
    const float* b1   = (const float*)d_in[6];
    const float* W2   = (const float*)d_in[7];
    float* out        = (float*)d_out;

    cudaFuncSetAttribute(xg_kernel, cudaFuncAttributeMaxDynamicSharedMemorySize, A_SMEM_BYTES);
    cudaFuncSetAttribute(lstm_rec_kernel, cudaFuncAttributeMaxDynamicSharedMemorySize, B_SMEM_BYTES);

    int dev = 0;
    cudaGetDevice(&dev);
    int sms = 148;
    cudaDeviceGetAttribute(&sms, cudaDevAttrMultiProcessorCount, dev);
    if (sms < 1) sms = 148;
    if (sms > NTILES) sms = NTILES;

    xg_kernel<<<sms, A_THREADS, A_SMEM_BYTES>>>(x, Wih0);
    lstm_rec_kernel<<<NBLK, B_THREADS, B_SMEM_BYTES>>>(Whh0, Wih1, Whh1, W1, b1, W2, out);
}